// round 6
// baseline (speedup 1.0000x reference)
#include <cuda_runtime.h>
#include <cuda_bf16.h>
#include <limits.h>

// Problem constants (from reference setup_inputs):
//   B=64 batches, K=16 candidates, L_cand=32, L_src=64, pad_id=0
#define B_SZ   64
#define K_SZ   16
#define LC_SZ  32
#define LS_SZ  64

#define FULL_MASK 0xFFFFFFFFu
#define HALF_MASK 0x0000FFFFu

// One CTA per batch, one warp per candidate k (16 warps = 512 threads).
// Lane l holds src pair (src[2l], src[2l+1]) via one LDG.64.
// Pre-barrier (all warps): dot[k] via candidate-broadcast SHFL loop,
//   c2 -> cn=sqrt(c2) (hoisted off tail), r2 partial: warp w broadcasts the
//   pairs of lanes w and w+16 -> src positions {2w,2w+1,32+2w,32+2w+1}
//   (full 64-position coverage across 16 warps); REDUX.
// Post-barrier (warp 0 only): r2 reduce, score, stable rank sort,
//   scores_sorted, winner token reload (L1-hot) + tokens/length writes.
__global__ void __launch_bounds__(512, 2)
ngram_rerank_kernel(const int* __restrict__ cand,   // [B, K, LC]
                    const int* __restrict__ src,    // [B, LS]
                    float* __restrict__ out_f,      // full fp32 layout, or null
                    int*   __restrict__ out_i)      // tokens-only int32, or null
{
    const int b    = blockIdx.x;
    const int tid  = threadIdx.x;
    const int warp = tid >> 5;     // candidate index k
    const int lane = tid & 31;

    __shared__ float sm_dotf[K_SZ];   // (float)dot[k]
    __shared__ float sm_cn[K_SZ];     // sqrt(c2[k])
    __shared__ int   sm_r2p[K_SZ];    // r2 partial per warp

    // ---- coalesced loads: src as int2 (one LDG.64), cand one LDG.32 ----
    const int2 sp = reinterpret_cast<const int2*>(src + b * LS_SZ)[lane];
    const int sA = sp.x;   // src[2*lane]
    const int sB = sp.y;   // src[2*lane+1]
    const int t  = cand[b * (K_SZ * LC_SZ) + warp * LC_SZ + lane];

    // ---- dot[k]: broadcast candidate tokens, compare vs sA/sB ----
    // pad candidates masked to -1 (never equals any src token >= 0)
    const int t_m = (t != 0) ? t : -1;
    int d = 0;
    #pragma unroll
    for (int i = 0; i < 32; i++) {
        const int cv = __shfl_sync(FULL_MASK, t_m, i);
        d += (cv == sA);
        d += (cv == sB);
    }

    // ---- ||c_k||^2 via match groups ----
    const unsigned mm = __match_any_sync(FULL_MASK, t);
    const int c2_val  = (t != 0) ? __popc(mm) : 0;

    // ---- r2 partial: warp w broadcasts pairs of lanes w and w+16 ----
    // covers src positions {2w, 2w+1, 32+2w, 32+2w+1}; 16 warps -> all 64.
    // lane-side sentinels: unique negatives per position (pads match nothing)
    const int sAm = (sA != 0) ? sA : ~(2 * lane);       // unique in [-64, -1]
    const int sBm = (sB != 0) ? sB : ~(2 * lane + 1);
    int cv0 = __shfl_sync(FULL_MASK, sAm, warp);        // src[2w]
    int cv1 = __shfl_sync(FULL_MASK, sBm, warp);        // src[2w+1]
    int cv2 = __shfl_sync(FULL_MASK, sAm, warp + 16);   // src[32+2w]
    int cv3 = __shfl_sync(FULL_MASK, sBm, warp + 16);   // src[32+2w+1]
    cv0 = (cv0 < 0) ? INT_MIN : cv0;    // broadcast-side pads match nothing
    cv1 = (cv1 < 0) ? INT_MIN : cv1;
    cv2 = (cv2 < 0) ? INT_MIN : cv2;
    cv3 = (cv3 < 0) ? INT_MIN : cv3;
    const int a = (cv0 == sAm) + (cv0 == sBm)
                + (cv1 == sAm) + (cv1 == sBm)
                + (cv2 == sAm) + (cv2 == sBm)
                + (cv3 == sAm) + (cv3 == sBm);

    const int dot = __reduce_add_sync(FULL_MASK, d);
    const int c2  = __reduce_add_sync(FULL_MASK, c2_val);
    const int r2p = __reduce_add_sync(FULL_MASK, a);

    if (lane == 0) {
        sm_dotf[warp] = (float)dot;            // I2F hoisted off tail
        sm_cn[warp]   = __fsqrt_rn((float)c2); // sqrt hoisted off tail
        sm_r2p[warp]  = r2p;
    }
    __syncthreads();

    if (warp != 0) return;   // warps 1..15 done

    // ---- warp 0 finishes alone ----
    int kwin_l = 0;
    if (lane < K_SZ) {
        const int r2 = __reduce_add_sync(HALF_MASK, sm_r2p[lane]);
        const float rn = __fsqrt_rn((float)r2);
        const float si = __fsub_rn(1.0f,
            __fdiv_rn(sm_dotf[lane], __fmul_rn(rn, sm_cn[lane])));

        // stable descending rank (matches jnp.argsort(-scores), stable)
        int rank = 0;
        #pragma unroll
        for (int j = 0; j < K_SZ; j++) {
            const float sj = __shfl_sync(HALF_MASK, si, j);
            rank += (sj > si) || (sj == si && j < lane);
        }
        if (out_f != nullptr)
            out_f[B_SZ * LC_SZ + B_SZ + b * K_SZ + rank] = si;  // scores_sorted

        const unsigned winb = __ballot_sync(HALF_MASK, rank == 0);
        kwin_l = __ffs(winb) - 1;
    }
    const int kwin = __shfl_sync(FULL_MASK, kwin_l, 0);

    // Winning candidate's tokens: line was just read by warp kwin -> L1 hit.
    const int tw = cand[b * (K_SZ * LC_SZ) + kwin * LC_SZ + lane];
    const unsigned nb = __ballot_sync(FULL_MASK, tw != 0);

    if (out_f != nullptr) {
        out_f[b * LC_SZ + lane] = (float)tw;                    // tokens
        if (lane == 0)
            out_f[B_SZ * LC_SZ + b] = (float)__popc(nb);        // length
    } else {
        out_i[b * LC_SZ + lane] = tw;
    }
}

extern "C" void kernel_launch(void* const* d_in, const int* in_sizes, int n_in,
                              void* d_out, int out_size)
{
    // Identify tensors by element count (robust to scalar inputs in the list):
    //   candidates: 64*16*32 = 32768,  src_ids: 64*64 = 4096
    const int* cand = nullptr;
    const int* src  = nullptr;
    for (int i = 0; i < n_in; i++) {
        if (in_sizes[i] == B_SZ * K_SZ * LC_SZ) cand = (const int*)d_in[i];
        else if (in_sizes[i] == B_SZ * LS_SZ)   src  = (const int*)d_in[i];
    }

    if (out_size == B_SZ * LC_SZ) {
        ngram_rerank_kernel<<<B_SZ, 512>>>(cand, src, nullptr, (int*)d_out);
    } else {
        ngram_rerank_kernel<<<B_SZ, 512>>>(cand, src, (float*)d_out, nullptr);
    }
}

// round 7
// speedup vs baseline: 1.0417x; 1.0417x over previous
#include <cuda_runtime.h>
#include <cuda_bf16.h>
#include <limits.h>

// Problem constants (from reference setup_inputs):
//   B=64 batches, K=16 candidates, L_cand=32, L_src=64, pad_id=0
#define B_SZ   64
#define K_SZ   16
#define LC_SZ  32
#define LS_SZ  64
#define NWARP  8          // 8 warps, 2 candidates per warp

#define FULL_MASK 0xFFFFFFFFu
#define HALF_MASK 0x0000FFFFu

// One CTA per batch, 256 threads (8 warps); warp w owns candidates w and w+8.
// Lane l holds src pair (src[2l], src[2l+1]) via one LDG.64.
// Pre-barrier: dot[k] via candidate-broadcast SHFL loop (two independent
//   chains pipelined per warp), c2 via match_any -> cn=sqrt(c2) hoisted,
//   r2 partial: warp w broadcasts pairs of lanes {w, w+8, w+16, w+24}
//   (8 src positions; 8 warps cover all 64). REDUX; lane0 -> smem; ONE barrier.
// Post-barrier (warp 0): r2 reduce, scores, stable rank sort, scores_sorted,
//   winner token reload (L1-hot) + tokens/length writes.
__global__ void __launch_bounds__(256, 4)
ngram_rerank_kernel(const int* __restrict__ cand,   // [B, K, LC]
                    const int* __restrict__ src,    // [B, LS]
                    float* __restrict__ out_f,      // full fp32 layout, or null
                    int*   __restrict__ out_i)      // tokens-only int32, or null
{
    const int b    = blockIdx.x;
    const int tid  = threadIdx.x;
    const int warp = tid >> 5;     // 0..7
    const int lane = tid & 31;

    __shared__ float sm_dotf[K_SZ];   // (float)dot[k]
    __shared__ float sm_cn[K_SZ];     // sqrt(c2[k])
    __shared__ int   sm_r2p[NWARP];   // r2 partial per warp

    // ---- coalesced loads: src as int2 (one LDG.64), two cand LDG.32 ----
    const int2 sp = reinterpret_cast<const int2*>(src + b * LS_SZ)[lane];
    const int sA = sp.x;   // src[2*lane]
    const int sB = sp.y;   // src[2*lane+1]
    const int* cb = cand + b * (K_SZ * LC_SZ);
    const int t0 = cb[warp * LC_SZ + lane];              // candidate k = warp
    const int t1 = cb[(warp + NWARP) * LC_SZ + lane];    // candidate k = warp+8

    // ---- dot: broadcast candidate tokens, compare vs sA/sB (2 chains) ----
    const int t0m = (t0 != 0) ? t0 : -1;
    const int t1m = (t1 != 0) ? t1 : -1;
    int d0 = 0, d1 = 0;
    #pragma unroll
    for (int i = 0; i < 32; i++) {
        const int cv0 = __shfl_sync(FULL_MASK, t0m, i);
        const int cv1 = __shfl_sync(FULL_MASK, t1m, i);
        d0 += (cv0 == sA);
        d0 += (cv0 == sB);
        d1 += (cv1 == sA);
        d1 += (cv1 == sB);
    }

    // ---- ||c_k||^2 via match groups (2 independent) ----
    const unsigned mm0 = __match_any_sync(FULL_MASK, t0);
    const unsigned mm1 = __match_any_sync(FULL_MASK, t1);
    const int c2v0 = (t0 != 0) ? __popc(mm0) : 0;
    const int c2v1 = (t1 != 0) ? __popc(mm1) : 0;

    // ---- r2 partial: warp w broadcasts pairs of lanes {w, w+8, w+16, w+24} ----
    // lane-side sentinels: unique negatives per position (pads match nothing)
    const int sAm = (sA != 0) ? sA : ~(2 * lane);       // unique in [-64, -1]
    const int sBm = (sB != 0) ? sB : ~(2 * lane + 1);
    int a = 0;
    #pragma unroll
    for (int q = 0; q < 4; q++) {
        int cvA = __shfl_sync(FULL_MASK, sAm, warp + q * NWARP);
        int cvB = __shfl_sync(FULL_MASK, sBm, warp + q * NWARP);
        cvA = (cvA < 0) ? INT_MIN : cvA;   // broadcast-side pads match nothing
        cvB = (cvB < 0) ? INT_MIN : cvB;
        a += (cvA == sAm) + (cvA == sBm) + (cvB == sAm) + (cvB == sBm);
    }

    const int dot0 = __reduce_add_sync(FULL_MASK, d0);
    const int dot1 = __reduce_add_sync(FULL_MASK, d1);
    const int c20  = __reduce_add_sync(FULL_MASK, c2v0);
    const int c21  = __reduce_add_sync(FULL_MASK, c2v1);
    const int r2p  = __reduce_add_sync(FULL_MASK, a);

    if (lane == 0) {
        sm_dotf[warp]         = (float)dot0;
        sm_dotf[warp + NWARP] = (float)dot1;
        sm_cn[warp]           = __fsqrt_rn((float)c20);
        sm_cn[warp + NWARP]   = __fsqrt_rn((float)c21);
        sm_r2p[warp]          = r2p;
    }
    __syncthreads();

    if (warp != 0) return;   // warps 1..7 done

    // ---- warp 0 finishes alone ----
    int kwin_l = 0;
    if (lane < K_SZ) {
        const int r2 = __reduce_add_sync(HALF_MASK,
                                         (lane < NWARP) ? sm_r2p[lane] : 0);
        const float rn = __fsqrt_rn((float)r2);
        const float si = __fsub_rn(1.0f,
            __fdiv_rn(sm_dotf[lane], __fmul_rn(rn, sm_cn[lane])));

        // stable descending rank (matches jnp.argsort(-scores), stable)
        int rank = 0;
        #pragma unroll
        for (int j = 0; j < K_SZ; j++) {
            const float sj = __shfl_sync(HALF_MASK, si, j);
            rank += (sj > si) || (sj == si && j < lane);
        }
        if (out_f != nullptr)
            out_f[B_SZ * LC_SZ + B_SZ + b * K_SZ + rank] = si;  // scores_sorted

        const unsigned winb = __ballot_sync(HALF_MASK, rank == 0);
        kwin_l = __ffs(winb) - 1;
    }
    const int kwin = __shfl_sync(FULL_MASK, kwin_l, 0);

    // Winning candidate's tokens: line was read this launch -> L1 hit.
    const int tw = cb[kwin * LC_SZ + lane];
    const unsigned nb = __ballot_sync(FULL_MASK, tw != 0);

    if (out_f != nullptr) {
        out_f[b * LC_SZ + lane] = (float)tw;                    // tokens
        if (lane == 0)
            out_f[B_SZ * LC_SZ + b] = (float)__popc(nb);        // length
    } else {
        out_i[b * LC_SZ + lane] = tw;
    }
}

extern "C" void kernel_launch(void* const* d_in, const int* in_sizes, int n_in,
                              void* d_out, int out_size)
{
    // Identify tensors by element count (robust to scalar inputs in the list):
    //   candidates: 64*16*32 = 32768,  src_ids: 64*64 = 4096
    const int* cand = nullptr;
    const int* src  = nullptr;
    for (int i = 0; i < n_in; i++) {
        if (in_sizes[i] == B_SZ * K_SZ * LC_SZ) cand = (const int*)d_in[i];
        else if (in_sizes[i] == B_SZ * LS_SZ)   src  = (const int*)d_in[i];
    }

    if (out_size == B_SZ * LC_SZ) {
        ngram_rerank_kernel<<<B_SZ, 256>>>(cand, src, nullptr, (int*)d_out);
    } else {
        ngram_rerank_kernel<<<B_SZ, 256>>>(cand, src, (float*)d_out, nullptr);
    }
}

// round 8
// speedup vs baseline: 1.0870x; 1.0435x over previous
#include <cuda_runtime.h>
#include <cuda_bf16.h>
#include <limits.h>

// Problem constants (from reference setup_inputs):
//   B=64 batches, K=16 candidates, L_cand=32, L_src=64, pad_id=0
//   vocab V=50257 < 2^16 -> tokens fit in 16 bits (packed compares safe)
#define B_SZ   64
#define K_SZ   16
#define LC_SZ  32
#define LS_SZ  64

#define FULL_MASK 0xFFFFFFFFu
#define HALF_MASK 0x0000FFFFu

// One CTA per batch, one warp per candidate k (16 warps = 512 threads).
// Lane l holds src pair (src[2l], src[2l+1]) packed into one reg (16b halves).
// Pre-barrier (all warps):
//   dot[k]: broadcast duplicated candidate halfwords, one __vcmpeq2 + packed
//           add per src pair (32 iters); cand pad -> 0xFFFF sentinel (> max
//           token, != src pad 0) so it never matches.
//   c2[k] : __match_any + popc -> cn = sqrt(c2) hoisted off the tail.
//   r2    : distributed — warp w broadcasts pairs of lanes w and w+16
//           (positions {2w,2w+1,32+2w,32+2w+1}; 16 warps cover all 64).
//   REDUX; lane0 -> smem; ONE barrier.
// Post-barrier (warp 0 only): r2 reduce, score, stable rank sort,
//   scores_sorted, winner token reload (L1-hot) + tokens/length writes.
__global__ void __launch_bounds__(512, 2)
ngram_rerank_kernel(const int* __restrict__ cand,   // [B, K, LC]
                    const int* __restrict__ src,    // [B, LS]
                    float* __restrict__ out_f,      // full fp32 layout, or null
                    int*   __restrict__ out_i)      // tokens-only int32, or null
{
    const int b    = blockIdx.x;
    const int tid  = threadIdx.x;
    const int warp = tid >> 5;     // candidate index k
    const int lane = tid & 31;

    __shared__ float sm_dotf[K_SZ];   // (float)dot[k]
    __shared__ float sm_cn[K_SZ];     // sqrt(c2[k])
    __shared__ int   sm_r2p[K_SZ];    // r2 partial per warp

    // ---- coalesced loads: src as int2 (one LDG.64), cand one LDG.32 ----
    const int2 sp = reinterpret_cast<const int2*>(src + b * LS_SZ)[lane];
    const int sA = sp.x;   // src[2*lane]
    const int sB = sp.y;   // src[2*lane+1]
    const int t  = cand[b * (K_SZ * LC_SZ) + warp * LC_SZ + lane];

    // ---- dot[k]: packed 16-bit compares ----
    // sPK: (sB<<16)|sA ; src pads stay 0 (valid cand tokens are >=1).
    // cand pad -> 0xFFFF sentinel (max valid token 50256 < 0xFFFF).
    const unsigned sPK  = ((unsigned)sB << 16) | ((unsigned)sA & 0xFFFFu);
    const unsigned t16  = (t != 0) ? (unsigned)t : 0xFFFFu;
    const unsigned tdup = t16 * 0x00010001u;   // duplicate into both halves
    unsigned dacc = 0;                          // per-half counts (<=32, no carry)
    #pragma unroll
    for (int i = 0; i < 32; i++) {
        const unsigned cv = __shfl_sync(FULL_MASK, tdup, i);
        dacc += (__vcmpeq2(cv, sPK) & 0x00010001u);
    }
    const int d = (int)((dacc & 0xFFFFu) + (dacc >> 16));

    // ---- ||c_k||^2 via match groups ----
    const unsigned mm = __match_any_sync(FULL_MASK, t);
    const int c2_val  = (t != 0) ? __popc(mm) : 0;

    // ---- r2 partial: warp w broadcasts pairs of lanes w and w+16 ----
    // covers src positions {2w, 2w+1, 32+2w, 32+2w+1}; 16 warps -> all 64.
    // lane-side sentinels: unique negatives per position (pads match nothing)
    const int sAm = (sA != 0) ? sA : ~(2 * lane);       // unique in [-64, -1]
    const int sBm = (sB != 0) ? sB : ~(2 * lane + 1);
    int cv0 = __shfl_sync(FULL_MASK, sAm, warp);        // src[2w]
    int cv1 = __shfl_sync(FULL_MASK, sBm, warp);        // src[2w+1]
    int cv2 = __shfl_sync(FULL_MASK, sAm, warp + 16);   // src[32+2w]
    int cv3 = __shfl_sync(FULL_MASK, sBm, warp + 16);   // src[32+2w+1]
    cv0 = (cv0 < 0) ? INT_MIN : cv0;    // broadcast-side pads match nothing
    cv1 = (cv1 < 0) ? INT_MIN : cv1;
    cv2 = (cv2 < 0) ? INT_MIN : cv2;
    cv3 = (cv3 < 0) ? INT_MIN : cv3;
    const int a = (cv0 == sAm) + (cv0 == sBm)
                + (cv1 == sAm) + (cv1 == sBm)
                + (cv2 == sAm) + (cv2 == sBm)
                + (cv3 == sAm) + (cv3 == sBm);

    const int dot = __reduce_add_sync(FULL_MASK, d);
    const int c2  = __reduce_add_sync(FULL_MASK, c2_val);
    const int r2p = __reduce_add_sync(FULL_MASK, a);

    if (lane == 0) {
        sm_dotf[warp] = (float)dot;            // I2F hoisted off tail
        sm_cn[warp]   = __fsqrt_rn((float)c2); // sqrt hoisted off tail
        sm_r2p[warp]  = r2p;
    }
    __syncthreads();

    if (warp != 0) return;   // warps 1..15 done

    // ---- warp 0 finishes alone ----
    int kwin_l = 0;
    if (lane < K_SZ) {
        const int r2 = __reduce_add_sync(HALF_MASK, sm_r2p[lane]);
        const float rn = __fsqrt_rn((float)r2);
        const float si = __fsub_rn(1.0f,
            __fdiv_rn(sm_dotf[lane], __fmul_rn(rn, sm_cn[lane])));

        // stable descending rank (matches jnp.argsort(-scores), stable)
        int rank = 0;
        #pragma unroll
        for (int j = 0; j < K_SZ; j++) {
            const float sj = __shfl_sync(HALF_MASK, si, j);
            rank += (sj > si) || (sj == si && j < lane);
        }
        if (out_f != nullptr)
            out_f[B_SZ * LC_SZ + B_SZ + b * K_SZ + rank] = si;  // scores_sorted

        const unsigned winb = __ballot_sync(HALF_MASK, rank == 0);
        kwin_l = __ffs(winb) - 1;
    }
    const int kwin = __shfl_sync(FULL_MASK, kwin_l, 0);

    // Winning candidate's tokens: line was just read by warp kwin -> L1 hit.
    const int tw = cand[b * (K_SZ * LC_SZ) + kwin * LC_SZ + lane];
    const unsigned nb = __ballot_sync(FULL_MASK, tw != 0);

    if (out_f != nullptr) {
        out_f[b * LC_SZ + lane] = (float)tw;                    // tokens
        if (lane == 0)
            out_f[B_SZ * LC_SZ + b] = (float)__popc(nb);        // length
    } else {
        out_i[b * LC_SZ + lane] = tw;
    }
}

extern "C" void kernel_launch(void* const* d_in, const int* in_sizes, int n_in,
                              void* d_out, int out_size)
{
    // Identify tensors by element count (robust to scalar inputs in the list):
    //   candidates: 64*16*32 = 32768,  src_ids: 64*64 = 4096
    const int* cand = nullptr;
    const int* src  = nullptr;
    for (int i = 0; i < n_in; i++) {
        if (in_sizes[i] == B_SZ * K_SZ * LC_SZ) cand = (const int*)d_in[i];
        else if (in_sizes[i] == B_SZ * LS_SZ)   src  = (const int*)d_in[i];
    }

    if (out_size == B_SZ * LC_SZ) {
        ngram_rerank_kernel<<<B_SZ, 512>>>(cand, src, nullptr, (int*)d_out);
    } else {
        ngram_rerank_kernel<<<B_SZ, 512>>>(cand, src, (float*)d_out, nullptr);
    }
}